// round 10
// baseline (speedup 1.0000x reference)
#include <cuda_runtime.h>
#include <cstdint>

// ============================================================================
// out[8192,4096] = sign(x) @ sign(w).   Exact integer arithmetic throughout.
//
// R9: warp-specialized dual-pipe hybrid (fixed R8 half-tile-load bug).
//   warps 0..7  : XOR+CSA popcount GEMM  (ALU pipe)   rows 0..5631
//                 streamed as (tile, half) steps of 32KB, double-buffered
//   warps 8..15 : legacy s8 mma.sync GEMM (emulated uops, fma pipe)
//                                                     rows 5632..8191
// ============================================================================

static constexpr int MDIM = 8192;
static constexpr int NDIM = 4096;
static constexpr int KDIM = 4096;
static constexpr int KW   = KDIM / 32;      // 128 words

// ---- popc path: rows 0..5631, 64x64 tiles ----
static constexpr int MT_P   = 88;           // 5632 / 64
static constexpr int NT_P   = 64;
static constexpr int TILES_P = MT_P * NT_P; // 5632
// step buffer: A half 16KB + B half 16KB
static constexpr int PSTEP_BYTES = 32768;
// ---- mma path: rows 5632..8191, 128x128 tiles ----
static constexpr int MT_S = 20;             // 2560 / 128
static constexpr int NT_S = 32;             // 4096 / 128
static constexpr int KT_S = 64;
static constexpr int A_TILE8 = 128 * 64;    // 8192 B
static constexpr int B_TILE8 = 128 * 64;    // 8192 B
static constexpr int STAGE8  = A_TILE8 + B_TILE8;       // 16384
static constexpr int GRID = MT_S * NT_S;    // 640 blocks

static constexpr int SMEM_POPC = 2 * PSTEP_BYTES;       // 65536
static constexpr int SMEM_MMA  = 4 * STAGE8;            // 65536
static constexpr int SMEM_TOTAL = SMEM_POPC + SMEM_MMA; // 131072

// Scratch
__device__ __align__(16) uint32_t g_xbits[(size_t)MT_P * KW * 64];           // 2.75 MB
__device__ __align__(16) uint32_t g_wbits[(size_t)NT_P * KW * 64];           // 2 MB
__device__ __align__(16) unsigned char g_xa8[(size_t)MT_S * KT_S * A_TILE8]; // 10 MB
__device__ __align__(16) unsigned char g_wb8[(size_t)NT_S * KT_S * B_TILE8]; // 16 MB

// ---------------------------------------------------------------------------
__device__ __forceinline__ uint32_t smem_u32(const void* p) {
    uint32_t a;
    asm("{ .reg .u64 t; cvta.to.shared.u64 t, %1; cvt.u32.u64 %0, t; }" : "=r"(a) : "l"(p));
    return a;
}
__device__ __forceinline__ uint32_t lds32(uint32_t addr) {
    uint32_t v;
    asm volatile("ld.shared.u32 %0, [%1];" : "=r"(v) : "r"(addr));
    return v;
}
__device__ __forceinline__ void cpasync16(uint32_t s, const void* g) {
    asm volatile("cp.async.cg.shared.global [%0], [%1], 16;" :: "r"(s), "l"(g));
}
#define CP_COMMIT() asm volatile("cp.async.commit_group;" ::: "memory")
#define CP_WAITN(n) asm volatile("cp.async.wait_group %0;" :: "n"(n) : "memory")
#define BAR_P() asm volatile("bar.sync 1, 256;" ::: "memory")   // popc warps
#define BAR_S() asm volatile("bar.sync 2, 256;" ::: "memory")   // mma warps

__device__ __forceinline__ void mma_s8(int* c, const uint32_t* a, const uint32_t* b) {
    asm volatile(
        "mma.sync.aligned.m16n8k32.row.col.s32.s8.s8.s32 "
        "{%0,%1,%2,%3}, {%4,%5,%6,%7}, {%8,%9}, {%0,%1,%2,%3};"
        : "+r"(c[0]), "+r"(c[1]), "+r"(c[2]), "+r"(c[3])
        : "r"(a[0]), "r"(a[1]), "r"(a[2]), "r"(a[3]), "r"(b[0]), "r"(b[1]));
}
__device__ __forceinline__ uint32_t swoff8(int r, int w) {
    int sw = (w >> 2) ^ ((r ^ (r >> 2)) & 3);
    return (uint32_t)(r * 64 + (sw << 4) + ((w & 3) << 2));
}
__device__ __forceinline__ unsigned char sgn_s8(float v) { return (v >= 0.0f) ? 0x01 : 0xFF; }

// ===========================================================================
// Prepasses
// ===========================================================================
__global__ void __launch_bounds__(256) k_packx(const float* __restrict__ x) {
    int m    = blockIdx.x * 8 + (threadIdx.x >> 5);    // 0..5631
    int lane = threadIdx.x & 31;
    const float* row = x + (size_t)m * KDIM;
    uint32_t mt = (uint32_t)m >> 6, ml = (uint32_t)m & 63u;
    uint32_t* dst = g_xbits + (size_t)mt * (KW * 64) + ml;
    #pragma unroll 4
    for (int w = 0; w < KW; w++) {
        float v = row[w * 32 + lane];
        uint32_t bits = __ballot_sync(0xffffffffu, v < 0.0f);
        if (lane == 0) dst[(size_t)w * 64] = bits;
    }
}

__global__ void __launch_bounds__(256) k_packw(const float* __restrict__ w) {
    uint32_t q  = blockIdx.x * 256u + threadIdx.x;   // 524288 threads
    uint32_t nl = q & 63u;
    uint32_t W  = (q >> 6) & 127u;
    uint32_t nt = q >> 13;
    uint32_t n  = nt * 64u + nl;
    uint32_t kb = W * 32u;
    uint32_t bits = 0;
    #pragma unroll
    for (int j = 0; j < 32; j++) {
        float v = w[(size_t)(kb + j) * NDIM + n];
        bits |= (v < 0.0f ? 1u : 0u) << j;
    }
    g_wbits[q] = bits;
}

__global__ void __launch_bounds__(256) k_binx8(const float* __restrict__ x) {
    uint32_t q = blockIdx.x * 256u + threadIdx.x;   // 2560*1024 threads
    uint32_t ml = q >> 10;                           // local row 0..2559
    uint32_t w = q & 1023u;
    uint32_t m = 5632u + ml;
    float4 v = *reinterpret_cast<const float4*>(x + (size_t)m * KDIM + (size_t)w * 4u);
    uint32_t word = (uint32_t)sgn_s8(v.x) | ((uint32_t)sgn_s8(v.y) << 8)
                  | ((uint32_t)sgn_s8(v.z) << 16) | ((uint32_t)sgn_s8(v.w) << 24);
    uint32_t kt = w >> 4, wl = w & 15u;
    size_t tile = ((size_t)((ml >> 7) * (uint32_t)KT_S + kt)) * (size_t)A_TILE8;
    *reinterpret_cast<uint32_t*>(g_xa8 + tile + swoff8((int)(ml & 127u), (int)wl)) = word;
}

// W -> s8 tiles [nt<32][kt<64][128 rows x 64B], transposed + swizzled.
__global__ void __launch_bounds__(256) k_binw8(const float* __restrict__ w) {
    __shared__ unsigned char s[128][68];
    uint32_t bid = blockIdx.x;                 // 2048 blocks
    uint32_t nt = bid & 31u;
    uint32_t kt = bid >> 5;
    uint32_t n0 = nt * 128u, k0 = kt * 64u;

    #pragma unroll
    for (int it = 0; it < 8; it++) {
        uint32_t q = threadIdx.x + it * 256u;          // 0..2047
        uint32_t kl = q >> 5;                           // 0..63
        uint32_t nl = (q & 31u) << 2;                   // 0..124
        float4 v = *reinterpret_cast<const float4*>(w + (size_t)(k0 + kl) * NDIM + n0 + nl);
        s[nl + 0][kl] = sgn_s8(v.x);
        s[nl + 1][kl] = sgn_s8(v.y);
        s[nl + 2][kl] = sgn_s8(v.z);
        s[nl + 3][kl] = sgn_s8(v.w);
    }
    __syncthreads();

    size_t tile = ((size_t)(nt * (uint32_t)KT_S + kt)) * (size_t)B_TILE8;
    #pragma unroll
    for (int it = 0; it < 8; it++) {
        uint32_t idx = threadIdx.x + it * 256u;        // word index 0..2047
        uint32_t r = idx >> 4, wd = idx & 15u;
        uint32_t word = *reinterpret_cast<const uint32_t*>(&s[r][wd * 4]);
        *reinterpret_cast<uint32_t*>(g_wb8 + tile + swoff8((int)r, (int)wd)) = word;
    }
}

// ===========================================================================
// Hybrid kernel: 512 threads, warps 0-7 popc / warps 8-15 s8 mma.
// ===========================================================================
__global__ void __launch_bounds__(512, 1) k_hybrid(float* __restrict__ out) {
    extern __shared__ uint32_t sm[];
    const int tid = threadIdx.x;
    const uint32_t bid = blockIdx.x;

    if (tid < 256) {
        // ================= POPC half (alu pipe) =================
        uint32_t* smP = sm;                      // 2 step-bufs x (A 4096w | B 4096w)
        const uint32_t sbP = smem_u32(smP);
        const int warp = tid >> 5;
        const int lane = tid & 31;
        const int mrow = (warp >> 2) * 32 + (lane >> 2) * 4;
        const int ncol = (warp & 3) * 16 + (lane & 3) * 4;

        // Issue one (tile, half) step: 16KB of A-half + 16KB of B-half.
        auto issue_half = [&](int tile, int half) {
            uint32_t base = sbP + (uint32_t)(half * PSTEP_BYTES);   // buf == half
            const char* aG = (const char*)(g_xbits + (size_t)(tile >> 6) * (KW * 64) + half * 4096);
            const char* bG = (const char*)(g_wbits + (size_t)(tile & 63) * (KW * 64) + half * 4096);
            #pragma unroll
            for (int i = 0; i < 4; i++) {
                int c = tid + i * 256;          // 0..1023 chunks of 16B = 16KB
                cpasync16(base + (uint32_t)(c * 16), aG + (size_t)c * 16);
                cpasync16(base + 16384u + (uint32_t)(c * 16), bG + (size_t)c * 16);
            }
        };

        int t0 = (int)bid;
        issue_half(t0, 0); CP_COMMIT();
        issue_half(t0, 1); CP_COMMIT();

        uint32_t ones[16], twos[16];
        int acc[16];
        #pragma unroll
        for (int o = 0; o < 16; o++) { ones[o] = 0; twos[o] = 0; acc[o] = 0; }

        for (int t = t0; t < TILES_P; t += GRID) {
            const bool have_next = (t + GRID < TILES_P);
            #pragma unroll
            for (int half = 0; half < 2; half++) {
                // wait for this step's group (order: steps complete FIFO)
                if (!have_next && half == 1) { CP_WAITN(0); }
                else                         { CP_WAITN(1); }
                BAR_P();

                const uint32_t* A = smP + half * (PSTEP_BYTES / 4);
                const uint32_t* B = A + 4096;

                #pragma unroll
                for (int grp = 0; grp < 16; grp++) {
                    const int gw = grp * 4;
                    uint32_t av[4][4], bv[4][4];
                    #pragma unroll
                    for (int w4 = 0; w4 < 4; w4++) {
                        uint4 Av = *reinterpret_cast<const uint4*>(A + (gw + w4) * 64 + mrow);
                        uint4 Bv = *reinterpret_cast<const uint4*>(B + (gw + w4) * 64 + ncol);
                        av[0][w4] = Av.x; av[1][w4] = Av.y; av[2][w4] = Av.z; av[3][w4] = Av.w;
                        bv[0][w4] = Bv.x; bv[1][w4] = Bv.y; bv[2][w4] = Bv.z; bv[3][w4] = Bv.w;
                    }
                    #pragma unroll
                    for (int mf = 0; mf < 4; mf++) {
                        #pragma unroll
                        for (int nf = 0; nf < 4; nf++) {
                            const int o = mf * 4 + nf;
                            uint32_t x0 = av[mf][0] ^ bv[nf][0];
                            uint32_t x1 = av[mf][1] ^ bv[nf][1];
                            uint32_t x2 = av[mf][2] ^ bv[nf][2];
                            uint32_t x3 = av[mf][3] ^ bv[nf][3];
                            uint32_t c0 = (ones[o] & x0) | (ones[o] & x1) | (x0 & x1);
                            ones[o] = ones[o] ^ x0 ^ x1;
                            uint32_t c1 = (ones[o] & x2) | (ones[o] & x3) | (x2 & x3);
                            ones[o] = ones[o] ^ x2 ^ x3;
                            uint32_t f = (twos[o] & c0) | (twos[o] & c1) | (c0 & c1);
                            twos[o] = twos[o] ^ c0 ^ c1;
                            acc[o] += __popc(f);
                        }
                    }
                }

                BAR_P();   // all popc threads done reading this buffer
                if (have_next) { issue_half(t + GRID, half); CP_COMMIT(); }
            }

            // Tile epilogue: D = 4*acc + 2*popc(twos) + popc(ones); dot = K - 2D.
            const uint32_t m0 = (uint32_t)(t >> 6) * 64u + (uint32_t)mrow;
            const uint32_t n0 = (uint32_t)(t & 63) * 64u + (uint32_t)ncol;
            #pragma unroll
            for (int mf = 0; mf < 4; mf++) {
                const int o = mf * 4;
                int D0 = (acc[o+0] << 2) + (__popc(twos[o+0]) << 1) + __popc(ones[o+0]);
                int D1 = (acc[o+1] << 2) + (__popc(twos[o+1]) << 1) + __popc(ones[o+1]);
                int D2 = (acc[o+2] << 2) + (__popc(twos[o+2]) << 1) + __popc(ones[o+2]);
                int D3 = (acc[o+3] << 2) + (__popc(twos[o+3]) << 1) + __popc(ones[o+3]);
                *reinterpret_cast<float4*>(out + (size_t)(m0 + (uint32_t)mf) * NDIM + n0) =
                    make_float4((float)(KDIM - 2 * D0), (float)(KDIM - 2 * D1),
                                (float)(KDIM - 2 * D2), (float)(KDIM - 2 * D3));
            }
            #pragma unroll
            for (int o = 0; o < 16; o++) { ones[o] = 0; twos[o] = 0; acc[o] = 0; }
        }
    } else {
        // ================= MMA half (emulated s8 mma, fma pipe) =============
        const uint32_t sb = smem_u32(sm) + (uint32_t)SMEM_POPC;
        const int ltid = tid - 256;
        const int warp = ltid >> 5;
        const int lane = ltid & 31;
        const int g    = lane >> 2;
        const int tig  = lane & 3;
        const int mbase = (warp >> 2) * 64;     // 2 m-warps
        const int nbase = (warp & 3) * 32;      // 4 n-warps, 32 cols each

        const uint32_t nt  = bid & 31u;
        const uint32_t mtl = bid >> 5;          // 0..19

        const unsigned char* aP = g_xa8 + (size_t)(mtl * (uint32_t)KT_S) * (size_t)A_TILE8;
        const unsigned char* bP = g_wb8 + (size_t)(nt  * (uint32_t)KT_S) * (size_t)B_TILE8;

        int acc[4][4][4];
        #pragma unroll
        for (int mf = 0; mf < 4; mf++)
            #pragma unroll
            for (int nf = 0; nf < 4; nf++)
                #pragma unroll
                for (int i = 0; i < 4; i++) acc[mf][nf][i] = 0;

        auto load_stage = [&](int s, int kt) {
            uint32_t base = sb + (uint32_t)(s * STAGE8);
            const unsigned char* as = aP + (size_t)kt * A_TILE8;
            const unsigned char* bs = bP + (size_t)kt * B_TILE8;
            #pragma unroll
            for (int i = 0; i < 2; i++) {               // A: 512 chunks
                int c = ltid + i * 256;
                cpasync16(base + (uint32_t)(c * 16), as + (size_t)c * 16);
            }
            #pragma unroll
            for (int i = 0; i < 2; i++) {               // B: 512 chunks
                int c = ltid + i * 256;
                cpasync16(base + (uint32_t)A_TILE8 + (uint32_t)(c * 16), bs + (size_t)c * 16);
            }
        };

        load_stage(0, 0); CP_COMMIT();
        load_stage(1, 1); CP_COMMIT();
        load_stage(2, 2); CP_COMMIT();

        for (int kt = 0; kt < KT_S; kt++) {
            CP_WAITN(2);
            BAR_S();
            if (kt + 3 < KT_S) load_stage((kt + 3) & 3, kt + 3);
            CP_COMMIT();

            const uint32_t base  = sb + (uint32_t)((kt & 3) * STAGE8);
            const uint32_t baseB = base + (uint32_t)A_TILE8;

            #pragma unroll
            for (int kf = 0; kf < 2; kf++) {
                const int w0 = kf * 8 + tig;
                const int w1 = kf * 8 + 4 + tig;
                uint32_t a[4][4];
                #pragma unroll
                for (int mf = 0; mf < 4; mf++) {
                    int r0 = mbase + mf * 16 + g;
                    a[mf][0] = lds32(base + swoff8(r0,     w0));
                    a[mf][1] = lds32(base + swoff8(r0 + 8, w0));
                    a[mf][2] = lds32(base + swoff8(r0,     w1));
                    a[mf][3] = lds32(base + swoff8(r0 + 8, w1));
                }
                uint32_t b[4][2];
                #pragma unroll
                for (int nf = 0; nf < 4; nf++) {
                    int r = nbase + nf * 8 + g;
                    b[nf][0] = lds32(baseB + swoff8(r, w0));
                    b[nf][1] = lds32(baseB + swoff8(r, w1));
                }
                #pragma unroll
                for (int mf = 0; mf < 4; mf++)
                    #pragma unroll
                    for (int nf = 0; nf < 4; nf++)
                        mma_s8(acc[mf][nf], a[mf], b[nf]);
            }
            BAR_S();
        }

        #pragma unroll
        for (int mf = 0; mf < 4; mf++) {
            int row = 5632 + (int)(mtl * 128u) + mbase + mf * 16 + g;
            float* o0 = out + (size_t)row * NDIM + nt * 128u + (uint32_t)(nbase + tig * 2);
            float* o1 = o0 + (size_t)8 * NDIM;
            #pragma unroll
            for (int nf = 0; nf < 4; nf++) {
                *reinterpret_cast<float2*>(o0 + nf * 8) =
                    make_float2((float)acc[mf][nf][0], (float)acc[mf][nf][1]);
                *reinterpret_cast<float2*>(o1 + nf * 8) =
                    make_float2((float)acc[mf][nf][2], (float)acc[mf][nf][3]);
            }
        }
    }
}

// ---------------------------------------------------------------------------
// Launch
// ---------------------------------------------------------------------------
extern "C" void kernel_launch(void* const* d_in, const int* in_sizes, int n_in,
                              void* d_out, int out_size) {
    const float* x = (const float*)d_in[0];
    const float* w = (const float*)d_in[1];
    float* out = (float*)d_out;
    (void)in_sizes; (void)n_in; (void)out_size;

    cudaFuncSetAttribute(k_hybrid, cudaFuncAttributeMaxDynamicSharedMemorySize, SMEM_TOTAL);

    k_packx<<<5632 / 8, 256>>>(x);                     // 704 blocks
    k_packw<<<(NT_P * KW * 64) / 256, 256>>>(w);       // 2048 blocks
    k_binx8<<<(2560 * 1024) / 256, 256>>>(x);          // 10240 blocks
    k_binw8<<<NT_S * KT_S, 256>>>(w);                  // 2048 blocks
    k_hybrid<<<GRID, 512, SMEM_TOTAL>>>(out);          // 640 blocks
}

// round 11
// speedup vs baseline: 1.3430x; 1.3430x over previous
#include <cuda_runtime.h>
#include <cstdint>

// ============================================================================
// out[8192,4096] = sign(x[8192,4096]) @ sign(w[4096,4096])
//
// Pure XOR+CSA popcount GEMM (ALU pipe), exact:
//   dot = 4096 - 2*popc(xbits ^ wbits)
// R10 = R7 (964us) with the I-cache fix: mainloop unrolled 8x instead of
// fully (SASS body ~13KB, fits I$-L1.5, vs ~100KB before).
// Inner math is at the Harley-Seal asymptote (3 alu-ops per word-pair);
// chip ALU-pipe floor ~717us.
// ============================================================================

static constexpr int MDIM = 8192;
static constexpr int NDIM = 4096;
static constexpr int KDIM = 4096;
static constexpr int KW   = KDIM / 32;   // 128 words per row

static constexpr int MT = MDIM / 64;     // 128 tiles (64 rows)
static constexpr int NT = NDIM / 64;     // 64 tiles (64 cols)

// Packed bit scratch, word-major per tile:
//   g_xbits[mt][w][m]  (mt<128, w<128, m<64)
//   g_wbits[nt][w][n]  (nt<64,  w<128, n<64)
__device__ __align__(16) uint32_t g_xbits[(size_t)MT * KW * 64];   // 4 MB
__device__ __align__(16) uint32_t g_wbits[(size_t)NT * KW * 64];   // 2 MB

// ---------------------------------------------------------------------------
__device__ __forceinline__ uint32_t smem_u32(const void* p) {
    uint32_t a;
    asm("{ .reg .u64 t; cvta.to.shared.u64 t, %1; cvt.u32.u64 %0, t; }" : "=r"(a) : "l"(p));
    return a;
}
__device__ __forceinline__ void cpasync16(uint32_t s, const void* g) {
    asm volatile("cp.async.cg.shared.global [%0], [%1], 16;" :: "r"(s), "l"(g));
}
#define CP_COMMIT() asm volatile("cp.async.commit_group;" ::: "memory")
#define CP_WAITN(n) asm volatile("cp.async.wait_group %0;" :: "n"(n) : "memory")

// ---------------------------------------------------------------------------
// Pack x: one warp per row; ballot packs 32 signs per word.
// ---------------------------------------------------------------------------
__global__ void __launch_bounds__(256) k_packx(const float* __restrict__ x) {
    int m    = blockIdx.x * 8 + (threadIdx.x >> 5);    // 0..8191
    int lane = threadIdx.x & 31;
    const float* row = x + (size_t)m * KDIM;
    uint32_t mt = (uint32_t)m >> 6, ml = (uint32_t)m & 63u;
    uint32_t* dst = g_xbits + (size_t)mt * (KW * 64) + ml;
    #pragma unroll 4
    for (int w = 0; w < KW; w++) {
        float v = row[w * 32 + lane];
        uint32_t bits = __ballot_sync(0xffffffffu, v < 0.0f);
        if (lane == 0) dst[(size_t)w * 64] = bits;
    }
}

// ---------------------------------------------------------------------------
// Pack w transposed: thread q builds word (column n, 32 consecutive k);
// output index == q (fully coalesced stores).
// ---------------------------------------------------------------------------
__global__ void __launch_bounds__(256) k_packw(const float* __restrict__ w) {
    uint32_t q  = blockIdx.x * 256u + threadIdx.x;   // 524288 threads
    uint32_t nl = q & 63u;
    uint32_t W  = (q >> 6) & 127u;
    uint32_t nt = q >> 13;
    uint32_t n  = nt * 64u + nl;
    uint32_t kb = W * 32u;
    uint32_t bits = 0;
    #pragma unroll
    for (int j = 0; j < 32; j++) {
        float v = w[(size_t)(kb + j) * NDIM + n];
        bits |= (v < 0.0f ? 1u : 0u) << j;
    }
    g_wbits[q] = bits;
}

// ---------------------------------------------------------------------------
// Binary GEMM: 64x64 tile, 256 threads, 16 outputs/thread (4m x 4n).
// Whole K (128 words) resident in smem; halves arrive via 2 cp.async groups.
// ---------------------------------------------------------------------------
__global__ void __launch_bounds__(256, 2) k_bgemm(float* __restrict__ out) {
    extern __shared__ uint32_t sm[];                 // [A: 128*64 | B: 128*64]
    uint32_t* smA = sm;
    uint32_t* smB = sm + KW * 64;
    const uint32_t sbA = smem_u32(smA);
    const uint32_t sbB = smem_u32(smB);

    const int tid  = threadIdx.x;
    const int warp = tid >> 5;
    const int lane = tid & 31;
    const int wm = warp >> 2;        // 0..1
    const int wn = warp & 3;         // 0..3
    const int mi = lane >> 2;        // 0..7
    const int ni = lane & 3;         // 0..3
    const int mrow = wm * 32 + mi * 4;   // first of 4 consecutive m rows
    const int ncol = wn * 16 + ni * 4;   // first of 4 consecutive n cols

    const uint32_t bid = blockIdx.x;
    const uint32_t ntb = bid & 63u;
    const uint32_t mtb = bid >> 6;

    const char* aG = (const char*)(g_xbits + (size_t)mtb * (KW * 64));
    const char* bG = (const char*)(g_wbits + (size_t)ntb * (KW * 64));

    // Issue both halves: half h = words [h*64, h*64+64), 16KB per matrix.
    #pragma unroll
    for (int h = 0; h < 2; h++) {
        #pragma unroll
        for (int i = 0; i < 4; i++) {
            int c = tid + i * 256;                   // 0..1023 16B-chunks
            cpasync16(sbA + (uint32_t)(h * 16384 + c * 16), aG + (size_t)h * 16384 + (size_t)c * 16);
            cpasync16(sbB + (uint32_t)(h * 16384 + c * 16), bG + (size_t)h * 16384 + (size_t)c * 16);
        }
        CP_COMMIT();
    }

    uint32_t ones[16], twos[16];
    int acc[16];
    #pragma unroll
    for (int o = 0; o < 16; o++) { ones[o] = 0; twos[o] = 0; acc[o] = 0; }

    CP_WAITN(1);
    __syncthreads();

    #pragma unroll 2
    for (int half = 0; half < 2; half++) {
        if (half == 1) { CP_WAITN(0); __syncthreads(); }

        // I$-friendly: unroll 8 of 16 -> body ~13KB SASS, fits L1.5.
        #pragma unroll 8
        for (int grp = 0; grp < 16; grp++) {
            const int gw = half * 64 + grp * 4;      // first word of group
            uint32_t av[4][4], bv[4][4];
            #pragma unroll
            for (int w4 = 0; w4 < 4; w4++) {
                uint4 A = *reinterpret_cast<const uint4*>(smA + (gw + w4) * 64 + mrow);
                uint4 B = *reinterpret_cast<const uint4*>(smB + (gw + w4) * 64 + ncol);
                av[0][w4] = A.x; av[1][w4] = A.y; av[2][w4] = A.z; av[3][w4] = A.w;
                bv[0][w4] = B.x; bv[1][w4] = B.y; bv[2][w4] = B.z; bv[3][w4] = B.w;
            }
            #pragma unroll
            for (int mf = 0; mf < 4; mf++) {
                #pragma unroll
                for (int nf = 0; nf < 4; nf++) {
                    const int o = mf * 4 + nf;
                    uint32_t x0 = av[mf][0] ^ bv[nf][0];
                    uint32_t x1 = av[mf][1] ^ bv[nf][1];
                    uint32_t x2 = av[mf][2] ^ bv[nf][2];
                    uint32_t x3 = av[mf][3] ^ bv[nf][3];
                    // CSA(ones, x0, x1) -> t0
                    uint32_t t0 = (ones[o] & x0) | (ones[o] & x1) | (x0 & x1);
                    ones[o] = ones[o] ^ x0 ^ x1;
                    // CSA(ones, x2, x3) -> t1
                    uint32_t t1 = (ones[o] & x2) | (ones[o] & x3) | (x2 & x3);
                    ones[o] = ones[o] ^ x2 ^ x3;
                    // CSA(twos, t0, t1) -> f (weight 4)
                    uint32_t f = (twos[o] & t0) | (twos[o] & t1) | (t0 & t1);
                    twos[o] = twos[o] ^ t0 ^ t1;
                    acc[o] += __popc(f);
                }
            }
        }
    }

    // Epilogue: D = 4*acc + 2*popc(twos) + popc(ones); dot = 4096 - 2D.
    const uint32_t m0 = mtb * 64u + (uint32_t)mrow;
    const uint32_t n0 = ntb * 64u + (uint32_t)ncol;
    #pragma unroll
    for (int mf = 0; mf < 4; mf++) {
        float4 v;
        {
            const int o = mf * 4;
            int D0 = (acc[o+0] << 2) + (__popc(twos[o+0]) << 1) + __popc(ones[o+0]);
            int D1 = (acc[o+1] << 2) + (__popc(twos[o+1]) << 1) + __popc(ones[o+1]);
            int D2 = (acc[o+2] << 2) + (__popc(twos[o+2]) << 1) + __popc(ones[o+2]);
            int D3 = (acc[o+3] << 2) + (__popc(twos[o+3]) << 1) + __popc(ones[o+3]);
            v = make_float4((float)(KDIM - 2 * D0), (float)(KDIM - 2 * D1),
                            (float)(KDIM - 2 * D2), (float)(KDIM - 2 * D3));
        }
        *reinterpret_cast<float4*>(out + (size_t)(m0 + (uint32_t)mf) * NDIM + n0) = v;
    }
}

// ---------------------------------------------------------------------------
// Launch
// ---------------------------------------------------------------------------
extern "C" void kernel_launch(void* const* d_in, const int* in_sizes, int n_in,
                              void* d_out, int out_size) {
    const float* x = (const float*)d_in[0];   // [8192, 4096]
    const float* w = (const float*)d_in[1];   // [4096, 4096] (k-major)
    float* out = (float*)d_out;               // [8192, 4096]
    (void)in_sizes; (void)n_in; (void)out_size;

    static constexpr int SMEM = 2 * KW * 64 * 4;   // 65536 B
    cudaFuncSetAttribute(k_bgemm, cudaFuncAttributeMaxDynamicSharedMemorySize, SMEM);

    k_packx<<<MDIM / 8, 256>>>(x);                 // 1024 blocks
    k_packw<<<(NT * KW * 64) / 256, 256>>>(w);     // 2048 blocks
    k_bgemm<<<MT * NT, 256, SMEM>>>(out);          // 8192 blocks
}